// round 3
// baseline (speedup 1.0000x reference)
#include <cuda_runtime.h>
#include <cstdint>

// Problem constants (fixed by the dataset)
#define EMBED_DIM   64
#define MAX_ITEMS   500096      // >= 500,000, padded
#define MAX_EDGES   2000128     // >= 2,000,000, padded
#define SCAN_BLOCK  1024
#define MAX_SCAN_BLOCKS 1024    // 500000/1024 = 489 blocks

// Scratch (device globals — no cudaMalloc allowed)
__device__ int g_cnt[MAX_ITEMS];        // in-degree per item (build only)
__device__ int g_rowptr[MAX_ITEMS];     // exclusive scan of counts
__device__ int g_cursor[MAX_ITEMS];     // fill cursor (copy of rowptr)
__device__ int g_srcid[MAX_EDGES];      // CSR values: user index per slot
__device__ int g_blocksums[MAX_SCAN_BLOCKS];
__device__ int g_blockoffs[MAX_SCAN_BLOCKS];

// ---------------------------------------------------------------------------
// 1) zero counts
__global__ void k_zero(int n_item) {
    int i = blockIdx.x * blockDim.x + threadIdx.x;
    if (i < n_item) g_cnt[i] = 0;
}

// 2) histogram of edge_dst
__global__ void k_hist(const int* __restrict__ dst, int E) {
    int i = blockIdx.x * blockDim.x + threadIdx.x;
    if (i < E) atomicAdd(&g_cnt[__ldg(&dst[i])], 1);
}

// 3) per-block exclusive scan (Hillis-Steele), emit block totals
__global__ __launch_bounds__(SCAN_BLOCK)
void k_scan1(int n) {
    __shared__ int sh[SCAN_BLOCK];
    int gid = blockIdx.x * SCAN_BLOCK + threadIdx.x;
    int v = (gid < n) ? g_cnt[gid] : 0;
    sh[threadIdx.x] = v;
    __syncthreads();
    #pragma unroll
    for (int off = 1; off < SCAN_BLOCK; off <<= 1) {
        int t = (threadIdx.x >= off) ? sh[threadIdx.x - off] : 0;
        __syncthreads();
        sh[threadIdx.x] += t;
        __syncthreads();
    }
    int incl = sh[threadIdx.x];
    if (gid < n) g_rowptr[gid] = incl - v;          // exclusive
    if (threadIdx.x == SCAN_BLOCK - 1) g_blocksums[blockIdx.x] = incl;
}

// 4) single-block exclusive scan of block sums
__global__ __launch_bounds__(SCAN_BLOCK)
void k_scan2(int nb) {
    __shared__ int sh[SCAN_BLOCK];
    int v = (threadIdx.x < nb) ? g_blocksums[threadIdx.x] : 0;
    sh[threadIdx.x] = v;
    __syncthreads();
    #pragma unroll
    for (int off = 1; off < SCAN_BLOCK; off <<= 1) {
        int t = (threadIdx.x >= off) ? sh[threadIdx.x - off] : 0;
        __syncthreads();
        sh[threadIdx.x] += t;
        __syncthreads();
    }
    if (threadIdx.x < nb) g_blockoffs[threadIdx.x] = sh[threadIdx.x] - v;
}

// 5) apply block offsets; init cursor
__global__ __launch_bounds__(SCAN_BLOCK)
void k_scan3(int n) {
    int gid = blockIdx.x * SCAN_BLOCK + threadIdx.x;
    if (gid < n) {
        int r = g_rowptr[gid] + g_blockoffs[blockIdx.x];
        g_rowptr[gid] = r;
        g_cursor[gid] = r;
    }
}

// 6) fill CSR slots with source user id
__global__ void k_fill(const int* __restrict__ src, const int* __restrict__ dst, int E) {
    int i = blockIdx.x * blockDim.x + threadIdx.x;
    if (i < E) {
        int pos = atomicAdd(&g_cursor[__ldg(&dst[i])], 1);
        g_srcid[pos] = __ldg(&src[i]);
    }
}

// 7) gather-mean: one warp per item, lane owns a float2 slice (2*32 = 64 dims).
//    deg derived from rowptr deltas (adjacent entries -> same cache line).
//    Indices loaded warp-uniform (broadcast), 4-way unrolled for MLP.
__global__ __launch_bounds__(256)
void k_gather(const float* __restrict__ user, float* __restrict__ out,
              int n_item, int E) {
    int warp_in_block = threadIdx.x >> 5;
    int lane = threadIdx.x & 31;
    int item = blockIdx.x * (blockDim.x >> 5) + warp_in_block;
    if (item >= n_item) return;

    int start = __ldg(&g_rowptr[item]);
    int end   = (item + 1 < n_item) ? __ldg(&g_rowptr[item + 1]) : E;
    int deg   = end - start;

    const float2* __restrict__ U = reinterpret_cast<const float2*>(user);

    float ax0 = 0.f, ay0 = 0.f, ax1 = 0.f, ay1 = 0.f;

    int j = 0;
    for (; j + 4 <= deg; j += 4) {
        // 4 independent index loads (warp-uniform broadcast)
        int u0 = __ldg(&g_srcid[start + j + 0]);
        int u1 = __ldg(&g_srcid[start + j + 1]);
        int u2 = __ldg(&g_srcid[start + j + 2]);
        int u3 = __ldg(&g_srcid[start + j + 3]);
        // 4 independent 256B coalesced row reads in flight
        float2 v0 = __ldg(&U[(size_t)u0 * 32 + lane]);
        float2 v1 = __ldg(&U[(size_t)u1 * 32 + lane]);
        float2 v2 = __ldg(&U[(size_t)u2 * 32 + lane]);
        float2 v3 = __ldg(&U[(size_t)u3 * 32 + lane]);
        ax0 += v0.x; ay0 += v0.y;
        ax1 += v1.x; ay1 += v1.y;
        ax0 += v2.x; ay0 += v2.y;
        ax1 += v3.x; ay1 += v3.y;
    }
    for (; j < deg; j++) {
        int u = __ldg(&g_srcid[start + j]);
        float2 v = __ldg(&U[(size_t)u * 32 + lane]);
        ax0 += v.x; ay0 += v.y;
    }

    float sc = (deg > 0) ? (1.0f / (float)deg) : 0.0f;
    float2 r;
    r.x = (ax0 + ax1) * sc;
    r.y = (ay0 + ay1) * sc;
    reinterpret_cast<float2*>(out)[(size_t)item * 32 + lane] = r;
}

// ---------------------------------------------------------------------------
extern "C" void kernel_launch(void* const* d_in, const int* in_sizes, int n_in,
                              void* d_out, int out_size) {
    const float* user_embed = (const float*)d_in[0];
    // d_in[1] (item_embed) unused by the reference computation
    const int* edge_src = (const int*)d_in[2];
    const int* edge_dst = (const int*)d_in[3];

    int n_item = in_sizes[1] / EMBED_DIM;   // 500,000
    int E      = in_sizes[2];               // 2,000,000

    float* out = (float*)d_out;

    int nb = (n_item + SCAN_BLOCK - 1) / SCAN_BLOCK;   // 489

    k_zero <<<(n_item + 255) / 256, 256>>>(n_item);
    k_hist <<<(E + 255) / 256, 256>>>(edge_dst, E);
    k_scan1<<<nb, SCAN_BLOCK>>>(n_item);
    k_scan2<<<1,  SCAN_BLOCK>>>(nb);
    k_scan3<<<nb, SCAN_BLOCK>>>(n_item);
    k_fill <<<(E + 255) / 256, 256>>>(edge_src, edge_dst, E);
    k_gather<<<(n_item + 7) / 8, 256>>>(user_embed, out, n_item, E);
}